// round 6
// baseline (speedup 1.0000x reference)
#include <cuda_runtime.h>
#include <math.h>

// Problem dims
#define S_ 2048
#define B_ 64
#define I_ 256
#define H_ 512
#define ROWS_ (S_ * B_)          // 131072
#define BH_ (B_ * H_)

// ---------------- scratch (no cudaMalloc allowed) ----------------
__device__ float g_buf0[(size_t)S_ * BH_];   // xb0 -> y0 (in place)
__device__ float g_buf1[(size_t)S_ * BH_];   // y1
__device__ float g_zero[16 * H_];            // stays zero (bss)
__device__ __align__(128) unsigned g_slots[128];   // [bg][hg] arrival rounds

// ---------------- packed f32x2 FMA ----------------
__device__ __forceinline__ void fma2(float2& d, float2 a, float2 b) {
    asm volatile(
        "{\n\t"
        ".reg .b64 ra, rb, rd;\n\t"
        "mov.b64 ra, {%2, %3};\n\t"
        "mov.b64 rb, {%4, %5};\n\t"
        "mov.b64 rd, {%0, %1};\n\t"
        "fma.rn.f32x2 rd, ra, rb, rd;\n\t"
        "mov.b64 {%0, %1}, rd;\n\t"
        "}"
        : "+f"(d.x), "+f"(d.y)
        : "f"(a.x), "f"(a.y), "f"(b.x), "f"(b.y));
}
__device__ __forceinline__ void fma4(float2& acc, float4 a, float4 w) {
    fma2(acc, make_float2(a.x, a.y), make_float2(w.x, w.y));
    fma2(acc, make_float2(a.z, a.w), make_float2(w.z, w.w));
}

__device__ __forceinline__ unsigned su32(const void* p) {
    return (unsigned)__cvta_generic_to_shared(p);
}
__device__ __forceinline__ void cp16(unsigned dst, const float* src) {
    asm volatile("cp.async.cg.shared.global [%0], [%1], 16;" :: "r"(dst), "l"(src));
}
#define CP_COMMIT() asm volatile("cp.async.commit_group;" ::: "memory")
#define CP_WAITG(n) asm volatile("cp.async.wait_group %0;" :: "n"(n) : "memory")

// ---------------- slot barrier ----------------
__device__ __forceinline__ void group_wait(const unsigned* slots, unsigned t) {
    if (threadIdx.x < 32) {
        const unsigned* p = slots + threadIdx.x;
        unsigned v;
        do {
            asm volatile("ld.relaxed.gpu.global.u32 %0, [%1];"
                         : "=r"(v) : "l"(p) : "memory");
        } while (__any_sync(0xffffffffu, v < t));
        asm volatile("fence.acq_rel.gpu;" ::: "memory");
    }
    __syncthreads();
}
__device__ __forceinline__ void group_arrive(unsigned* slot, unsigned v) {
    __syncthreads();   // all stores of this CTA issued
    if (threadIdx.x == 0)
        asm volatile("st.release.gpu.global.u32 [%0], %1;"
                     :: "l"(slot), "r"(v) : "memory");
}

// ---------------- counter init (graph-replay safe reset) ----------------
__global__ void init_ctrs_kernel() {
    g_slots[threadIdx.x] = 0u;
}

// ---------------- projection GEMM (layer 0 only) ----------------
#define TM 64
#define TN 64
#define KC 64
#define SAST 66

__global__ void __launch_bounds__(256) proj_kernel(
    const float* __restrict__ A,
    const float* __restrict__ W,
    const int*   __restrict__ Wmask,
    const float* __restrict__ bias1,
    const float* __restrict__ bias2,
    int K)
{
    __shared__ float SA[TM * SAST];
    __shared__ float SW[TN * SAST];

    float* C = g_buf0;
    const int m0 = blockIdx.x * TM;
    const int n0 = blockIdx.y * TN;
    const int tid = threadIdx.x;
    const int tx = tid & 15;
    const int ty = tid >> 4;

    float2 acc[4][4];
#pragma unroll
    for (int i = 0; i < 4; i++)
#pragma unroll
        for (int j = 0; j < 4; j++) acc[i][j] = make_float2(0.f, 0.f);

    for (int kc = 0; kc < K; kc += KC) {
#pragma unroll
        for (int t = tid; t < TM * 16; t += 256) {
            int r = t >> 4, q = t & 15;
            float4 v = *(const float4*)&A[(size_t)(m0 + r) * K + kc + 4 * q];
            int o = r * SAST + 4 * q;
            *(float2*)&SA[o]     = make_float2(v.x, v.y);
            *(float2*)&SA[o + 2] = make_float2(v.z, v.w);
        }
#pragma unroll
        for (int t = tid; t < TN * 16; t += 256) {
            int r = t >> 4, q = t & 15;
            size_t g = (size_t)(n0 + r) * K + kc + 4 * q;
            float4 v = *(const float4*)&W[g];
            int4  mm = *(const int4*)&Wmask[g];
            int o = r * SAST + 4 * q;
            SW[o]     = v.x * (float)mm.x;
            SW[o + 1] = v.y * (float)mm.y;
            SW[o + 2] = v.z * (float)mm.z;
            SW[o + 3] = v.w * (float)mm.w;
        }
        __syncthreads();

#pragma unroll 8
        for (int k = 0; k < KC; k += 2) {
            float2 a[4], w[4];
#pragma unroll
            for (int i = 0; i < 4; i++) a[i] = *(float2*)&SA[(ty + 16 * i) * SAST + k];
#pragma unroll
            for (int j = 0; j < 4; j++) w[j] = *(float2*)&SW[(tx + 16 * j) * SAST + k];
#pragma unroll
            for (int i = 0; i < 4; i++)
#pragma unroll
                for (int j = 0; j < 4; j++) fma2(acc[i][j], a[i], w[j]);
        }
        __syncthreads();
    }

#pragma unroll
    for (int j = 0; j < 4; j++) {
        int n = n0 + tx + 16 * j;
        float bb = bias1[n] + bias2[n];
#pragma unroll
        for (int i = 0; i < 4; i++) {
            int m = m0 + ty + 16 * i;
            C[(size_t)m * H_ + n] = acc[i][j].x + acc[i][j].y + bb;
        }
    }
}

// ---------------- fused 2-layer recurrence (R4 skeleton) -----------------
// step t: L0 computes y0[t] (t<S), L1 computes y1[t-1] (t>=1).
// 128 CTAs = 4 bg x 32 hg, 256 threads, weights in registers, one barrier/step.
#define NCTA 128
#define RTH  256
#define HST  520
#define RST  272
#define RED_G (32 * RST)
#define HS0_OFF 0
#define HS1_OFF (16 * HST)
#define RED_OFF (32 * HST)
#define SMEM_FLOATS (RED_OFF + 3 * RED_G)
#define RNN_SMEM_BYTES (SMEM_FLOATS * 4)

__global__ void __launch_bounds__(RTH, 1) rnn_pipe_kernel(
    const float* __restrict__ Whh0, const int* __restrict__ m_hh0,
    const float* __restrict__ Wih1, const int* __restrict__ m_ih1,
    const float* __restrict__ Whh1, const int* __restrict__ m_hh1,
    const float* __restrict__ b_ih1, const float* __restrict__ b_hh1)
{
    extern __shared__ float smem[];
    float* hs0 = smem + HS0_OFF;     // [16][HST]
    float* hs1 = smem + HS1_OFF;     // [16][HST]
    float* red = smem + RED_OFF;     // [3][32][RST]

    const int bg = blockIdx.x >> 5;
    const int hg = blockIdx.x & 31;
    const int b0 = bg * 16;
    const int h0 = hg * 16;
    const int tid = threadIdx.x;
    const int tx = tid & 7;           // col pair
    const int ks = tid >> 3;          // 0..31, k-slice of 16
    const int k0 = ks * 16;

    const unsigned* slots = &g_slots[bg * 32];
    unsigned* my_slot = &g_slots[bg * 32 + hg];

    // ---- permanent register weights ----
    float4 wr[3][2][4];
    {
        const float* Wp[3] = { Whh0, Wih1, Whh1 };
        const int*   Mp[3] = { m_hh0, m_ih1, m_hh1 };
#pragma unroll
        for (int g = 0; g < 3; g++)
#pragma unroll
            for (int c = 0; c < 2; c++) {
                size_t ro = (size_t)(h0 + 2 * tx + c) * H_ + k0;
#pragma unroll
                for (int q = 0; q < 4; q++) {
                    float4 v = *(const float4*)&Wp[g][ro + 4 * q];
                    int4  mm = *(const int4*)&Mp[g][ro + 4 * q];
                    wr[g][c][q] = make_float4(v.x * (float)mm.x, v.y * (float)mm.y,
                                              v.z * (float)mm.z, v.w * (float)mm.w);
                }
            }
    }

    const int orow = tid >> 4;
    const int ocol = tid & 15;
    const size_t offO = (size_t)(b0 + orow) * H_ + (h0 + ocol);
    const float bL1 = __ldg(&b_ih1[h0 + ocol]) + __ldg(&b_hh1[h0 + ocol]);
    float xv = __ldg(&g_buf0[offO]);

    const unsigned hs0_b = su32(hs0);
    const unsigned hs1_b = su32(hs1);
    const int sts0 = 0 * RED_G + ks * RST + 2 * tx;
    const int sts1 = 1 * RED_G + ks * RST + 2 * tx;
    const int sts2 = 2 * RED_G + ks * RST + 2 * tx;

    for (int t = 0; t <= S_; ++t) {
        float s0 = 0.f, s1 = 0.f, s2 = 0.f;

        if (t > 0) {
            group_wait(slots, (unsigned)t);

            // ---- issue staging: hs0 in 2 chunks, hs1 in 1 ----
            const float* src0 = g_buf0 + (size_t)(t - 1) * BH_ + (size_t)b0 * H_;
#pragma unroll
            for (int i = 0; i < 4; i++) {               // rows 0..7
                int idx = tid + i * RTH;
                int r = idx >> 7, q = idx & 127;
                cp16(hs0_b + (unsigned)(r * HST + 4 * q) * 4u, src0 + (size_t)idx * 4);
            }
            CP_COMMIT();
#pragma unroll
            for (int i = 4; i < 8; i++) {               // rows 8..15
                int idx = tid + i * RTH;
                int r = idx >> 7, q = idx & 127;
                cp16(hs0_b + (unsigned)(r * HST + 4 * q) * 4u, src0 + (size_t)idx * 4);
            }
            CP_COMMIT();
            const float* src1 = (t >= 2)
                ? g_buf1 + (size_t)(t - 2) * BH_ + (size_t)b0 * H_ : g_zero;
#pragma unroll
            for (int i = 0; i < 8; i++) {
                int idx = tid + i * RTH;
                int r = idx >> 7, q = idx & 127;
                cp16(hs1_b + (unsigned)(r * HST + 4 * q) * 4u, src1 + (size_t)idx * 4);
            }
            CP_COMMIT();

            // ---- gemm01 rows 0..7 (hs0 chunk 1) ----
            CP_WAITG(2);
            __syncthreads();
#pragma unroll 4
            for (int r = 0; r < 8; r++) {
                const float* ap = &hs0[r * HST + k0];
                float4 a0 = *(const float4*)&ap[0];
                float4 a1 = *(const float4*)&ap[4];
                float4 a2 = *(const float4*)&ap[8];
                float4 a3 = *(const float4*)&ap[12];
                float2 p00 = make_float2(0.f, 0.f), p01 = make_float2(0.f, 0.f);
                float2 p10 = make_float2(0.f, 0.f), p11 = make_float2(0.f, 0.f);
                fma4(p00, a0, wr[0][0][0]); fma4(p01, a0, wr[0][1][0]);
                fma4(p10, a0, wr[1][0][0]); fma4(p11, a0, wr[1][1][0]);
                fma4(p00, a1, wr[0][0][1]); fma4(p01, a1, wr[0][1][1]);
                fma4(p10, a1, wr[1][0][1]); fma4(p11, a1, wr[1][1][1]);
                fma4(p00, a2, wr[0][0][2]); fma4(p01, a2, wr[0][1][2]);
                fma4(p10, a2, wr[1][0][2]); fma4(p11, a2, wr[1][1][2]);
                fma4(p00, a3, wr[0][0][3]); fma4(p01, a3, wr[0][1][3]);
                fma4(p10, a3, wr[1][0][3]); fma4(p11, a3, wr[1][1][3]);
                *(float2*)&red[sts0 + r * 16] = make_float2(p00.x + p00.y, p01.x + p01.y);
                *(float2*)&red[sts1 + r * 16] = make_float2(p10.x + p10.y, p11.x + p11.y);
            }

            // ---- gemm01 rows 8..15 (hs0 chunk 2) ----
            CP_WAITG(1);
            __syncthreads();
#pragma unroll 4
            for (int r = 8; r < 16; r++) {
                const float* ap = &hs0[r * HST + k0];
                float4 a0 = *(const float4*)&ap[0];
                float4 a1 = *(const float4*)&ap[4];
                float4 a2 = *(const float4*)&ap[8];
                float4 a3 = *(const float4*)&ap[12];
                float2 p00 = make_float2(0.f, 0.f), p01 = make_float2(0.f, 0.f);
                float2 p10 = make_float2(0.f, 0.f), p11 = make_float2(0.f, 0.f);
                fma4(p00, a0, wr[0][0][0]); fma4(p01, a0, wr[0][1][0]);
                fma4(p10, a0, wr[1][0][0]); fma4(p11, a0, wr[1][1][0]);
                fma4(p00, a1, wr[0][0][1]); fma4(p01, a1, wr[0][1][1]);
                fma4(p10, a1, wr[1][0][1]); fma4(p11, a1, wr[1][1][1]);
                fma4(p00, a2, wr[0][0][2]); fma4(p01, a2, wr[0][1][2]);
                fma4(p10, a2, wr[1][0][2]); fma4(p11, a2, wr[1][1][2]);
                fma4(p00, a3, wr[0][0][3]); fma4(p01, a3, wr[0][1][3]);
                fma4(p10, a3, wr[1][0][3]); fma4(p11, a3, wr[1][1][3]);
                *(float2*)&red[sts0 + r * 16] = make_float2(p00.x + p00.y, p01.x + p01.y);
                *(float2*)&red[sts1 + r * 16] = make_float2(p10.x + p10.y, p11.x + p11.y);
            }

            // ---- gemm2 (hs1) ----
            CP_WAITG(0);
            __syncthreads();
#pragma unroll 4
            for (int r = 0; r < 16; r++) {
                const float* ap = &hs1[r * HST + k0];
                float4 a0 = *(const float4*)&ap[0];
                float4 a1 = *(const float4*)&ap[4];
                float4 a2 = *(const float4*)&ap[8];
                float4 a3 = *(const float4*)&ap[12];
                float2 p20 = make_float2(0.f, 0.f), p21 = make_float2(0.f, 0.f);
                fma4(p20, a0, wr[2][0][0]); fma4(p21, a0, wr[2][1][0]);
                fma4(p20, a1, wr[2][0][1]); fma4(p21, a1, wr[2][1][1]);
                fma4(p20, a2, wr[2][0][2]); fma4(p21, a2, wr[2][1][2]);
                fma4(p20, a3, wr[2][0][3]); fma4(p21, a3, wr[2][1][3]);
                *(float2*)&red[sts2 + r * 16] = make_float2(p20.x + p20.y, p21.x + p21.y);
            }
            __syncthreads();

            // ---- reductions ----
#pragma unroll
            for (int k = 0; k < 32; k++) {
                s0 += red[0 * RED_G + k * RST + tid];
                s1 += red[1 * RED_G + k * RST + tid];
                s2 += red[2 * RED_G + k * RST + tid];
            }
        }

        if (t < S_) {
            g_buf0[(size_t)t * BH_ + offO] = tanhf(s0 + xv);
            if (t + 1 < S_)
                xv = __ldg(&g_buf0[(size_t)(t + 1) * BH_ + offO]);
        }
        if (t > 0) {
            g_buf1[(size_t)(t - 1) * BH_ + offO] = tanhf(s1 + s2 + bL1);
        }

        group_arrive(my_slot, (unsigned)(t + 1));
    }
}

// ---------------- final copy ----------------
__global__ void copy_out_kernel(float* __restrict__ dst) {
    int i = blockIdx.x * blockDim.x + threadIdx.x;
    dst[i] = g_buf1[(size_t)(S_ - 1) * BH_ + i];
}

// ---------------- launch ----------------
extern "C" void kernel_launch(void* const* d_in, const int* in_sizes, int n_in,
                              void* d_out, int out_size) {
    const float* x       = (const float*)d_in[0];
    const float* W_ih0   = (const float*)d_in[1];
    const float* W_hh0   = (const float*)d_in[2];
    const float* b_ih0   = (const float*)d_in[3];
    const float* b_hh0   = (const float*)d_in[4];
    const float* W_ih1   = (const float*)d_in[5];
    const float* W_hh1   = (const float*)d_in[6];
    const float* b_ih1   = (const float*)d_in[7];
    const float* b_hh1   = (const float*)d_in[8];
    const int*   m_ih0   = (const int*)d_in[9];
    const int*   m_hh0   = (const int*)d_in[10];
    const int*   m_ih1   = (const int*)d_in[11];
    const int*   m_hh1   = (const int*)d_in[12];
    float* out = (float*)d_out;

    static bool attr_set = false;
    if (!attr_set) {
        cudaFuncSetAttribute(rnn_pipe_kernel,
                             cudaFuncAttributeMaxDynamicSharedMemorySize,
                             RNN_SMEM_BYTES);
        attr_set = true;
    }

    init_ctrs_kernel<<<1, 128>>>();

    dim3 pgrid(ROWS_ / TM, H_ / TN);
    proj_kernel<<<pgrid, 256>>>(x, W_ih0, m_ih0, b_ih0, b_hh0, I_);

    rnn_pipe_kernel<<<NCTA, RTH, RNN_SMEM_BYTES>>>(
        W_hh0, m_hh0, W_ih1, m_ih1, W_hh1, m_hh1, b_ih1, b_hh1);

    copy_out_kernel<<<(BH_) / 256, 256>>>(out);
}

// round 7
// speedup vs baseline: 1.2511x; 1.2511x over previous
#include <cuda_runtime.h>
#include <math.h>

// Problem dims
#define S_ 2048
#define B_ 64
#define I_ 256
#define H_ 512
#define ROWS_ (S_ * B_)          // 131072
#define BH_ (B_ * H_)

// ---------------- scratch (no cudaMalloc allowed) ----------------
__device__ float g_buf0[(size_t)S_ * BH_];   // xb0 -> y0 (in place)
__device__ float g_buf1[(size_t)S_ * BH_];   // y1
__device__ float g_zero[16 * H_];            // stays zero (bss)
__device__ unsigned g_ctr[128];              // per-bgroup counter at bg*32
__device__ unsigned g_flag[128];             // per-bgroup release flag at bg*32

// ---------------- packed f32x2 FMA ----------------
__device__ __forceinline__ void fma2(float2& d, float2 a, float2 b) {
    asm volatile(
        "{\n\t"
        ".reg .b64 ra, rb, rd;\n\t"
        "mov.b64 ra, {%2, %3};\n\t"
        "mov.b64 rb, {%4, %5};\n\t"
        "mov.b64 rd, {%0, %1};\n\t"
        "fma.rn.f32x2 rd, ra, rb, rd;\n\t"
        "mov.b64 {%0, %1}, rd;\n\t"
        "}"
        : "+f"(d.x), "+f"(d.y)
        : "f"(a.x), "f"(a.y), "f"(b.x), "f"(b.y));
}
__device__ __forceinline__ void fma4(float2& acc, float4 a, float4 w) {
    fma2(acc, make_float2(a.x, a.y), make_float2(w.x, w.y));
    fma2(acc, make_float2(a.z, a.w), make_float2(w.z, w.w));
}

__device__ __forceinline__ unsigned su32(const void* p) {
    return (unsigned)__cvta_generic_to_shared(p);
}
__device__ __forceinline__ void cp16(unsigned dst, const float* src) {
    asm volatile("cp.async.cg.shared.global [%0], [%1], 16;" :: "r"(dst), "l"(src));
}
#define CP_COMMIT() asm volatile("cp.async.commit_group;" ::: "memory")
#define CP_WAIT0()  asm volatile("cp.async.wait_group 0;" ::: "memory")
#define CP_WAIT1()  asm volatile("cp.async.wait_group 1;" ::: "memory")

// ---------------- counter init (graph-replay safe reset) ----------------
__global__ void init_ctrs_kernel() {
    int i = threadIdx.x;
    g_ctr[i] = 0u;
    g_flag[i] = 0u;
}

// ---------------- projection GEMM (layer 0 only) ----------------
#define TM 64
#define TN 64
#define KC 64
#define SAST 66

__global__ void __launch_bounds__(256) proj_kernel(
    const float* __restrict__ A,
    const float* __restrict__ W,
    const int*   __restrict__ Wmask,
    const float* __restrict__ bias1,
    const float* __restrict__ bias2,
    int K)
{
    __shared__ float SA[TM * SAST];
    __shared__ float SW[TN * SAST];

    float* C = g_buf0;
    const int m0 = blockIdx.x * TM;
    const int n0 = blockIdx.y * TN;
    const int tid = threadIdx.x;
    const int tx = tid & 15;
    const int ty = tid >> 4;

    float2 acc[4][4];
#pragma unroll
    for (int i = 0; i < 4; i++)
#pragma unroll
        for (int j = 0; j < 4; j++) acc[i][j] = make_float2(0.f, 0.f);

    for (int kc = 0; kc < K; kc += KC) {
#pragma unroll
        for (int t = tid; t < TM * 16; t += 256) {
            int r = t >> 4, q = t & 15;
            float4 v = *(const float4*)&A[(size_t)(m0 + r) * K + kc + 4 * q];
            int o = r * SAST + 4 * q;
            *(float2*)&SA[o]     = make_float2(v.x, v.y);
            *(float2*)&SA[o + 2] = make_float2(v.z, v.w);
        }
#pragma unroll
        for (int t = tid; t < TN * 16; t += 256) {
            int r = t >> 4, q = t & 15;
            size_t g = (size_t)(n0 + r) * K + kc + 4 * q;
            float4 v = *(const float4*)&W[g];
            int4  mm = *(const int4*)&Wmask[g];
            int o = r * SAST + 4 * q;
            SW[o]     = v.x * (float)mm.x;
            SW[o + 1] = v.y * (float)mm.y;
            SW[o + 2] = v.z * (float)mm.z;
            SW[o + 3] = v.w * (float)mm.w;
        }
        __syncthreads();

#pragma unroll 8
        for (int k = 0; k < KC; k += 2) {
            float2 a[4], w[4];
#pragma unroll
            for (int i = 0; i < 4; i++) a[i] = *(float2*)&SA[(ty + 16 * i) * SAST + k];
#pragma unroll
            for (int j = 0; j < 4; j++) w[j] = *(float2*)&SW[(tx + 16 * j) * SAST + k];
#pragma unroll
            for (int i = 0; i < 4; i++)
#pragma unroll
                for (int j = 0; j < 4; j++) fma2(acc[i][j], a[i], w[j]);
        }
        __syncthreads();
    }

#pragma unroll
    for (int j = 0; j < 4; j++) {
        int n = n0 + tx + 16 * j;
        float bb = bias1[n] + bias2[n];
#pragma unroll
        for (int i = 0; i < 4; i++) {
            int m = m0 + ty + 16 * i;
            C[(size_t)m * H_ + n] = acc[i][j].x + acc[i][j].y + bb;
        }
    }
}

// ---------------- fused 2-layer recurrence (R4 skeleton, swizzled smem) ---
// step t: L0 computes y0[t] (t<S), L1 computes y1[t-1] (t>=1).
// 128 CTAs = 4 bg x 32 hg, 256 threads, weights in registers.
// hs: k-chunk of 16 floats padded to stride 20 -> conflict-free LDS.128.
// red: [g][ks][r][col], ks-stride 264 (== 8 mod 32) -> minimal-phase STS.64.
#define NCTA 128
#define RTH  256
#define GSZ  32
#define HSK  20              // floats per 16-float k-chunk (padded)
#define HST  (32 * HSK)      // 640: hs row stride
#define RSK  264             // red ks stride
#define RED_G (32 * RSK)     // 8448 floats per gemm
#define HS0_OFF 0
#define HS1_OFF (16 * HST)
#define RED_OFF (32 * HST)
#define SMEM_FLOATS (RED_OFF + 3 * RED_G)
#define RNN_SMEM_BYTES (SMEM_FLOATS * 4)   // 183296 B

__global__ void __launch_bounds__(RTH, 1) rnn_pipe_kernel(
    const float* __restrict__ Whh0, const int* __restrict__ m_hh0,
    const float* __restrict__ Wih1, const int* __restrict__ m_ih1,
    const float* __restrict__ Whh1, const int* __restrict__ m_hh1,
    const float* __restrict__ b_ih1, const float* __restrict__ b_hh1)
{
    extern __shared__ float smem[];
    float* hs0 = smem + HS0_OFF;     // [16][HST]
    float* hs1 = smem + HS1_OFF;     // [16][HST]
    float* red = smem + RED_OFF;     // [3][32][16*16 pad to RSK]

    const int bg = blockIdx.x >> 5;
    const int hg = blockIdx.x & 31;
    const int b0 = bg * 16;
    const int h0 = hg * 16;
    const int tid = threadIdx.x;
    const int tx = tid & 7;           // col pair
    const int ks = tid >> 3;          // 0..31, k-slice of 16
    const int k0 = ks * 16;           // k position in weights (unpadded)

    unsigned* ctr  = &g_ctr[bg * GSZ];
    unsigned* flag = &g_flag[bg * GSZ];

    // ---- permanent register weights ----
    float4 wr[3][2][4];
    {
        const float* Wp[3] = { Whh0, Wih1, Whh1 };
        const int*   Mp[3] = { m_hh0, m_ih1, m_hh1 };
#pragma unroll
        for (int g = 0; g < 3; g++)
#pragma unroll
            for (int c = 0; c < 2; c++) {
                size_t ro = (size_t)(h0 + 2 * tx + c) * H_ + k0;
#pragma unroll
                for (int q = 0; q < 4; q++) {
                    float4 v = *(const float4*)&Wp[g][ro + 4 * q];
                    int4  mm = *(const int4*)&Mp[g][ro + 4 * q];
                    wr[g][c][q] = make_float4(v.x * (float)mm.x, v.y * (float)mm.y,
                                              v.z * (float)mm.z, v.w * (float)mm.w);
                }
            }
    }

    const int orow = tid >> 4;
    const int ocol = tid & 15;
    const size_t offO = (size_t)(b0 + orow) * H_ + (h0 + ocol);
    const float bL1 = __ldg(&b_ih1[h0 + ocol]) + __ldg(&b_hh1[h0 + ocol]);
    float xv = __ldg(&g_buf0[offO]);

    const unsigned hs0_b = su32(hs0);
    const unsigned hs1_b = su32(hs1);
    const int ksk = ks * HSK;                         // padded k offset in hs rows
    const int sts0 = 0 * RED_G + ks * RSK + 2 * tx;   // + r*16 at use
    const int sts1 = 1 * RED_G + ks * RSK + 2 * tx;
    const int sts2 = 2 * RED_G + ks * RSK + 2 * tx;

    for (int t = 0; t <= S_; ++t) {
        if (t > 0) {
            // wait for step t-1 of this batch-group (all threads spin)
            unsigned f;
            do {
                asm volatile("ld.acquire.gpu.global.u32 %0, [%1];"
                             : "=r"(f) : "l"(flag) : "memory");
            } while (f < (unsigned)t);

            // stage hs0 = y0[t-1] (swizzled: chunk qg>>2 at stride HSK)
            {
                const float* src = g_buf0 + (size_t)(t - 1) * BH_ + (size_t)b0 * H_;
#pragma unroll
                for (int i = 0; i < 8; i++) {
                    int idx = tid + i * RTH;             // 0..2047 16B chunks
                    int r = idx >> 7, qg = idx & 127;
                    int w = r * HST + (qg >> 2) * HSK + (qg & 3) * 4;
                    cp16(hs0_b + (unsigned)w * 4u, src + (size_t)idx * 4);
                }
            }
            CP_COMMIT();
            // stage hs1 = y1[t-2] (zeros at t==1)
            {
                const float* src = (t >= 2)
                    ? g_buf1 + (size_t)(t - 2) * BH_ + (size_t)b0 * H_ : g_zero;
#pragma unroll
                for (int i = 0; i < 8; i++) {
                    int idx = tid + i * RTH;
                    int r = idx >> 7, qg = idx & 127;
                    int w = r * HST + (qg >> 2) * HSK + (qg & 3) * 4;
                    cp16(hs1_b + (unsigned)w * 4u, src + (size_t)idx * 4);
                }
            }
            CP_COMMIT();

            CP_WAIT1();              // hs0 ready
            __syncthreads();

            // gemm0 (Whh0) + gemm1 (Wih1) over hs0 rows
#pragma unroll 4
            for (int r = 0; r < 16; r++) {
                const float* ap = &hs0[r * HST + ksk];
                float4 a0 = *(const float4*)&ap[0];
                float4 a1 = *(const float4*)&ap[4];
                float4 a2 = *(const float4*)&ap[8];
                float4 a3 = *(const float4*)&ap[12];
                float2 p00 = make_float2(0.f, 0.f), p01 = make_float2(0.f, 0.f);
                float2 p10 = make_float2(0.f, 0.f), p11 = make_float2(0.f, 0.f);
                fma4(p00, a0, wr[0][0][0]); fma4(p01, a0, wr[0][1][0]);
                fma4(p10, a0, wr[1][0][0]); fma4(p11, a0, wr[1][1][0]);
                fma4(p00, a1, wr[0][0][1]); fma4(p01, a1, wr[0][1][1]);
                fma4(p10, a1, wr[1][0][1]); fma4(p11, a1, wr[1][1][1]);
                fma4(p00, a2, wr[0][0][2]); fma4(p01, a2, wr[0][1][2]);
                fma4(p10, a2, wr[1][0][2]); fma4(p11, a2, wr[1][1][2]);
                fma4(p00, a3, wr[0][0][3]); fma4(p01, a3, wr[0][1][3]);
                fma4(p10, a3, wr[1][0][3]); fma4(p11, a3, wr[1][1][3]);
                *(float2*)&red[sts0 + r * 16] =
                    make_float2(p00.x + p00.y, p01.x + p01.y);
                *(float2*)&red[sts1 + r * 16] =
                    make_float2(p10.x + p10.y, p11.x + p11.y);
            }

            CP_WAIT0();              // hs1 ready
            __syncthreads();

            // gemm2 (Whh1) over hs1 rows
#pragma unroll 4
            for (int r = 0; r < 16; r++) {
                const float* ap = &hs1[r * HST + ksk];
                float4 a0 = *(const float4*)&ap[0];
                float4 a1 = *(const float4*)&ap[4];
                float4 a2 = *(const float4*)&ap[8];
                float4 a3 = *(const float4*)&ap[12];
                float2 p20 = make_float2(0.f, 0.f), p21 = make_float2(0.f, 0.f);
                fma4(p20, a0, wr[2][0][0]); fma4(p21, a0, wr[2][1][0]);
                fma4(p20, a1, wr[2][0][1]); fma4(p21, a1, wr[2][1][1]);
                fma4(p20, a2, wr[2][0][2]); fma4(p21, a2, wr[2][1][2]);
                fma4(p20, a3, wr[2][0][3]); fma4(p21, a3, wr[2][1][3]);
                *(float2*)&red[sts2 + r * 16] =
                    make_float2(p20.x + p20.y, p21.x + p21.y);
            }
            __syncthreads();
        }

        // 32-way k-slice reduction (1 output per thread)
        float s0 = 0.f, s1 = 0.f, s2 = 0.f;
        if (t > 0) {
#pragma unroll
            for (int k = 0; k < 32; k++) {
                s0 += red[0 * RED_G + k * RSK + tid];
                s1 += red[1 * RED_G + k * RSK + tid];
                s2 += red[2 * RED_G + k * RSK + tid];
            }
        }

        if (t < S_) {
            float y0 = tanhf(s0 + xv);
            g_buf0[(size_t)t * BH_ + offO] = y0;
            if (t + 1 < S_)
                xv = __ldg(&g_buf0[(size_t)(t + 1) * BH_ + offO]);
        }
        if (t > 0) {
            float y1 = tanhf(s1 + s2 + bL1);
            g_buf1[(size_t)(t - 1) * BH_ + offO] = y1;
        }

        // group barrier arrival (R4 pattern: atomic counter + release flag)
        __syncthreads();
        if (tid == 0) {
            unsigned old;
            asm volatile("atom.acq_rel.gpu.global.add.u32 %0, [%1], 1;"
                         : "=r"(old) : "l"(ctr) : "memory");
            if (old == (unsigned)((t + 1) * GSZ - 1)) {
                asm volatile("st.release.gpu.global.u32 [%0], %1;"
                             :: "l"(flag), "r"((unsigned)(t + 1)) : "memory");
            }
        }
    }
}

// ---------------- final copy ----------------
__global__ void copy_out_kernel(float* __restrict__ dst) {
    int i = blockIdx.x * blockDim.x + threadIdx.x;
    dst[i] = g_buf1[(size_t)(S_ - 1) * BH_ + i];
}

// ---------------- launch ----------------
extern "C" void kernel_launch(void* const* d_in, const int* in_sizes, int n_in,
                              void* d_out, int out_size) {
    const float* x       = (const float*)d_in[0];
    const float* W_ih0   = (const float*)d_in[1];
    const float* W_hh0   = (const float*)d_in[2];
    const float* b_ih0   = (const float*)d_in[3];
    const float* b_hh0   = (const float*)d_in[4];
    const float* W_ih1   = (const float*)d_in[5];
    const float* W_hh1   = (const float*)d_in[6];
    const float* b_ih1   = (const float*)d_in[7];
    const float* b_hh1   = (const float*)d_in[8];
    const int*   m_ih0   = (const int*)d_in[9];
    const int*   m_hh0   = (const int*)d_in[10];
    const int*   m_ih1   = (const int*)d_in[11];
    const int*   m_hh1   = (const int*)d_in[12];
    float* out = (float*)d_out;

    static bool attr_set = false;
    if (!attr_set) {
        cudaFuncSetAttribute(rnn_pipe_kernel,
                             cudaFuncAttributeMaxDynamicSharedMemorySize,
                             RNN_SMEM_BYTES);
        attr_set = true;
    }

    init_ctrs_kernel<<<1, 128>>>();

    dim3 pgrid(ROWS_ / TM, H_ / TN);
    proj_kernel<<<pgrid, 256>>>(x, W_ih0, m_ih0, b_ih0, b_hh0, I_);

    rnn_pipe_kernel<<<NCTA, RTH, RNN_SMEM_BYTES>>>(
        W_hh0, m_hh0, W_ih1, m_ih1, W_hh1, m_hh1, b_ih1, b_hh1);

    copy_out_kernel<<<(BH_) / 256, 256>>>(out);
}

// round 8
// speedup vs baseline: 1.4269x; 1.1405x over previous
#include <cuda_runtime.h>
#include <math.h>

// Problem dims
#define S_ 2048
#define B_ 64
#define I_ 256
#define H_ 512
#define ROWS_ (S_ * B_)          // 131072
#define BH_ (B_ * H_)

// ---------------- scratch (no cudaMalloc allowed) ----------------
__device__ float g_buf0[(size_t)S_ * BH_];   // xb0 -> y0 (in place)
__device__ float g_buf1[(size_t)S_ * BH_];   // y1
__device__ float g_zero[16 * H_];            // stays zero (bss)
__device__ unsigned g_ctr[256];              // per-bgroup counter at bg*32
__device__ unsigned g_flag[256];             // per-bgroup release flag at bg*32

// ---------------- packed f32x2 FMA ----------------
__device__ __forceinline__ void fma2(float2& d, float2 a, float2 b) {
    asm volatile(
        "{\n\t"
        ".reg .b64 ra, rb, rd;\n\t"
        "mov.b64 ra, {%2, %3};\n\t"
        "mov.b64 rb, {%4, %5};\n\t"
        "mov.b64 rd, {%0, %1};\n\t"
        "fma.rn.f32x2 rd, ra, rb, rd;\n\t"
        "mov.b64 {%0, %1}, rd;\n\t"
        "}"
        : "+f"(d.x), "+f"(d.y)
        : "f"(a.x), "f"(a.y), "f"(b.x), "f"(b.y));
}
__device__ __forceinline__ void fma4(float2& acc, float4 a, float4 w) {
    fma2(acc, make_float2(a.x, a.y), make_float2(w.x, w.y));
    fma2(acc, make_float2(a.z, a.w), make_float2(w.z, w.w));
}

__device__ __forceinline__ unsigned su32(const void* p) {
    return (unsigned)__cvta_generic_to_shared(p);
}
__device__ __forceinline__ void cp16(unsigned dst, const float* src) {
    asm volatile("cp.async.cg.shared.global [%0], [%1], 16;" :: "r"(dst), "l"(src));
}
#define CP_COMMIT() asm volatile("cp.async.commit_group;" ::: "memory")
#define CP_WAIT0()  asm volatile("cp.async.wait_group 0;" ::: "memory")
#define CP_WAIT1()  asm volatile("cp.async.wait_group 1;" ::: "memory")

// ---------------- counter init (graph-replay safe reset) ----------------
__global__ void init_ctrs_kernel() {
    int i = threadIdx.x;
    g_ctr[i] = 0u;
    g_flag[i] = 0u;
}

// ---------------- projection GEMM (layer 0 only) ----------------
#define TM 64
#define TN 64
#define KC 64
#define SAST 66

__global__ void __launch_bounds__(256) proj_kernel(
    const float* __restrict__ A,
    const float* __restrict__ W,
    const int*   __restrict__ Wmask,
    const float* __restrict__ bias1,
    const float* __restrict__ bias2,
    int K)
{
    __shared__ float SA[TM * SAST];
    __shared__ float SW[TN * SAST];

    float* C = g_buf0;
    const int m0 = blockIdx.x * TM;
    const int n0 = blockIdx.y * TN;
    const int tid = threadIdx.x;
    const int tx = tid & 15;
    const int ty = tid >> 4;

    float2 acc[4][4];
#pragma unroll
    for (int i = 0; i < 4; i++)
#pragma unroll
        for (int j = 0; j < 4; j++) acc[i][j] = make_float2(0.f, 0.f);

    for (int kc = 0; kc < K; kc += KC) {
#pragma unroll
        for (int t = tid; t < TM * 16; t += 256) {
            int r = t >> 4, q = t & 15;
            float4 v = *(const float4*)&A[(size_t)(m0 + r) * K + kc + 4 * q];
            int o = r * SAST + 4 * q;
            *(float2*)&SA[o]     = make_float2(v.x, v.y);
            *(float2*)&SA[o + 2] = make_float2(v.z, v.w);
        }
#pragma unroll
        for (int t = tid; t < TN * 16; t += 256) {
            int r = t >> 4, q = t & 15;
            size_t g = (size_t)(n0 + r) * K + kc + 4 * q;
            float4 v = *(const float4*)&W[g];
            int4  mm = *(const int4*)&Wmask[g];
            int o = r * SAST + 4 * q;
            SW[o]     = v.x * (float)mm.x;
            SW[o + 1] = v.y * (float)mm.y;
            SW[o + 2] = v.z * (float)mm.z;
            SW[o + 3] = v.w * (float)mm.w;
        }
        __syncthreads();

#pragma unroll 8
        for (int k = 0; k < KC; k += 2) {
            float2 a[4], w[4];
#pragma unroll
            for (int i = 0; i < 4; i++) a[i] = *(float2*)&SA[(ty + 16 * i) * SAST + k];
#pragma unroll
            for (int j = 0; j < 4; j++) w[j] = *(float2*)&SW[(tx + 16 * j) * SAST + k];
#pragma unroll
            for (int i = 0; i < 4; i++)
#pragma unroll
                for (int j = 0; j < 4; j++) fma2(acc[i][j], a[i], w[j]);
        }
        __syncthreads();
    }

#pragma unroll
    for (int j = 0; j < 4; j++) {
        int n = n0 + tx + 16 * j;
        float bb = bias1[n] + bias2[n];
#pragma unroll
        for (int i = 0; i < 4; i++) {
            int m = m0 + ty + 16 * i;
            C[(size_t)m * H_ + n] = acc[i][j].x + acc[i][j].y + bb;
        }
    }
}

// ---------------- fused 2-layer recurrence: 8 bg x 16 hg retiling ---------
// step t: L0 computes y0[t] (t<S), L1 computes y1[t-1] (t>=1).
// CTA = 8 batch rows x 32 cols, 256 threads: col = tid&31, ks = tid>>5 (8
// slices of 64 k). Weights (3 x 64 floats) in registers. Sync group = 16 CTAs.
#define NCTA 128
#define RTH  256
#define GSZ  16
#define BROWS 8
#define BCOLS 32
#define HS0_OFF 0                    // [8][512]
#define HS1_OFF 4096                 // [8][512]
#define RED01_OFF 8192               // [8][256][2]
#define RED2_OFF 12288               // [8][256]
#define SMEM_FLOATS 14336
#define RNN_SMEM_BYTES (SMEM_FLOATS * 4)   // 57344 B

__global__ void __launch_bounds__(RTH, 1) rnn_pipe_kernel(
    const float* __restrict__ Whh0, const int* __restrict__ m_hh0,
    const float* __restrict__ Wih1, const int* __restrict__ m_ih1,
    const float* __restrict__ Whh1, const int* __restrict__ m_hh1,
    const float* __restrict__ b_ih1, const float* __restrict__ b_hh1)
{
    extern __shared__ float smem[];
    float* hs0   = smem + HS0_OFF;
    float* hs1   = smem + HS1_OFF;
    float* red01 = smem + RED01_OFF;
    float* red2  = smem + RED2_OFF;

    const int bg = blockIdx.x >> 4;   // 0..7  (8 batch rows each)
    const int hg = blockIdx.x & 15;   // 0..15 (32 cols each)
    const int b0 = bg * BROWS;
    const int h0 = hg * BCOLS;
    const int tid = threadIdx.x;
    const int col = tid & 31;         // output col within tile
    const int ks  = tid >> 5;         // 0..7, 64-k slice
    const int k0  = ks * 64;

    unsigned* ctr  = &g_ctr[bg * 32];
    unsigned* flag = &g_flag[bg * 32];

    // ---- permanent register weights: 16 float4 per gemm (64 k) ----
    float4 wr0[16], wr1[16], wr2[16];
    {
        size_t ro = (size_t)(h0 + col) * H_ + k0;
#pragma unroll
        for (int q = 0; q < 16; q++) {
            float4 v; int4 mm;
            v = *(const float4*)&Whh0[ro + 4 * q];
            mm = *(const int4*)&m_hh0[ro + 4 * q];
            wr0[q] = make_float4(v.x * (float)mm.x, v.y * (float)mm.y,
                                 v.z * (float)mm.z, v.w * (float)mm.w);
            v = *(const float4*)&Wih1[ro + 4 * q];
            mm = *(const int4*)&m_ih1[ro + 4 * q];
            wr1[q] = make_float4(v.x * (float)mm.x, v.y * (float)mm.y,
                                 v.z * (float)mm.z, v.w * (float)mm.w);
            v = *(const float4*)&Whh1[ro + 4 * q];
            mm = *(const int4*)&m_hh1[ro + 4 * q];
            wr2[q] = make_float4(v.x * (float)mm.x, v.y * (float)mm.y,
                                 v.z * (float)mm.z, v.w * (float)mm.w);
        }
    }

    // output mapping: o = tid -> (row tid>>5, col tid&31)
    const int orow = tid >> 5;
    const int ocol = tid & 31;
    const size_t offO = (size_t)(b0 + orow) * H_ + (h0 + ocol);
    const float bL1 = __ldg(&b_ih1[h0 + ocol]) + __ldg(&b_hh1[h0 + ocol]);
    float xv = __ldg(&g_buf0[offO]);

    const unsigned hs0_b = su32(hs0);
    const unsigned hs1_b = su32(hs1);

    for (int t = 0; t <= S_; ++t) {
        float s0 = 0.f, s1 = 0.f, s2 = 0.f;

        if (t > 0) {
            // wait for step t-1 of this batch-group (all threads spin)
            unsigned f;
            do {
                asm volatile("ld.acquire.gpu.global.u32 %0, [%1];"
                             : "=r"(f) : "l"(flag) : "memory");
            } while (f < (unsigned)t);

            // stage hs0 = y0[t-1][b0..b0+8][0..512): 16KB contiguous
            {
                const float* src = g_buf0 + (size_t)(t - 1) * BH_ + (size_t)b0 * H_;
#pragma unroll
                for (int i = 0; i < 4; i++) {
                    int idx = tid + i * RTH;             // 0..1023 16B chunks
                    cp16(hs0_b + (unsigned)idx * 16u, src + (size_t)idx * 4);
                }
            }
            CP_COMMIT();
            // stage hs1 = y1[t-2] (zeros at t==1)
            {
                const float* src = (t >= 2)
                    ? g_buf1 + (size_t)(t - 2) * BH_ + (size_t)b0 * H_ : g_zero;
#pragma unroll
                for (int i = 0; i < 4; i++) {
                    int idx = tid + i * RTH;
                    cp16(hs1_b + (unsigned)idx * 16u, src + (size_t)idx * 4);
                }
            }
            CP_COMMIT();

            CP_WAIT1();              // hs0 ready
            __syncthreads();

            // gemm0 (Whh0) + gemm1 (Wih1) over hs0 rows; LDS is full-warp
            // broadcast (warp = one ks, 32 cols)
#pragma unroll 2
            for (int r = 0; r < BROWS; r++) {
                const float* ap = &hs0[r * H_ + k0];
                float2 u0 = make_float2(0.f, 0.f);
                float2 u1 = make_float2(0.f, 0.f);
#pragma unroll
                for (int q = 0; q < 16; q++) {
                    float4 a = *(const float4*)&ap[4 * q];
                    fma4(u0, a, wr0[q]);
                    fma4(u1, a, wr1[q]);
                }
                *(float2*)&red01[(ks * 256 + r * BCOLS + col) * 2] =
                    make_float2(u0.x + u0.y, u1.x + u1.y);
            }

            CP_WAIT0();              // hs1 ready
            __syncthreads();

            // gemm2 (Whh1) over hs1 rows
#pragma unroll 2
            for (int r = 0; r < BROWS; r++) {
                const float* ap = &hs1[r * H_ + k0];
                float2 u2 = make_float2(0.f, 0.f);
#pragma unroll
                for (int q = 0; q < 16; q++) {
                    float4 a = *(const float4*)&ap[4 * q];
                    fma4(u2, a, wr2[q]);
                }
                red2[ks * 256 + r * BCOLS + col] = u2.x + u2.y;
            }
            __syncthreads();

            // 8-way k-slice reduction (1 output per thread)
#pragma unroll
            for (int k = 0; k < 8; k++) {
                float2 v = *(const float2*)&red01[(k * 256 + tid) * 2];
                s0 += v.x;
                s1 += v.y;
                s2 += red2[k * 256 + tid];
            }
        }

        if (t < S_) {
            float y0 = tanhf(s0 + xv);
            g_buf0[(size_t)t * BH_ + offO] = y0;
            if (t + 1 < S_)
                xv = __ldg(&g_buf0[(size_t)(t + 1) * BH_ + offO]);
        }
        if (t > 0) {
            float y1 = tanhf(s1 + s2 + bL1);
            g_buf1[(size_t)(t - 1) * BH_ + offO] = y1;
        }

        // group barrier arrival (atomic counter + release flag, 16 CTAs)
        __syncthreads();
        if (tid == 0) {
            unsigned old;
            asm volatile("atom.acq_rel.gpu.global.add.u32 %0, [%1], 1;"
                         : "=r"(old) : "l"(ctr) : "memory");
            if (old == (unsigned)((t + 1) * GSZ - 1)) {
                asm volatile("st.release.gpu.global.u32 [%0], %1;"
                             :: "l"(flag), "r"((unsigned)(t + 1)) : "memory");
            }
        }
    }
}

// ---------------- final copy ----------------
__global__ void copy_out_kernel(float* __restrict__ dst) {
    int i = blockIdx.x * blockDim.x + threadIdx.x;
    dst[i] = g_buf1[(size_t)(S_ - 1) * BH_ + i];
}

// ---------------- launch ----------------
extern "C" void kernel_launch(void* const* d_in, const int* in_sizes, int n_in,
                              void* d_out, int out_size) {
    const float* x       = (const float*)d_in[0];
    const float* W_ih0   = (const float*)d_in[1];
    const float* W_hh0   = (const float*)d_in[2];
    const float* b_ih0   = (const float*)d_in[3];
    const float* b_hh0   = (const float*)d_in[4];
    const float* W_ih1   = (const float*)d_in[5];
    const float* W_hh1   = (const float*)d_in[6];
    const float* b_ih1   = (const float*)d_in[7];
    const float* b_hh1   = (const float*)d_in[8];
    const int*   m_ih0   = (const int*)d_in[9];
    const int*   m_hh0   = (const int*)d_in[10];
    const int*   m_ih1   = (const int*)d_in[11];
    const int*   m_hh1   = (const int*)d_in[12];
    float* out = (float*)d_out;

    static bool attr_set = false;
    if (!attr_set) {
        cudaFuncSetAttribute(rnn_pipe_kernel,
                             cudaFuncAttributeMaxDynamicSharedMemorySize,
                             RNN_SMEM_BYTES);
        attr_set = true;
    }

    init_ctrs_kernel<<<1, 256>>>();

    dim3 pgrid(ROWS_ / TM, H_ / TN);
    proj_kernel<<<pgrid, 256>>>(x, W_ih0, m_ih0, b_ih0, b_hh0, I_);

    rnn_pipe_kernel<<<NCTA, RTH, RNN_SMEM_BYTES>>>(
        W_hh0, m_hh0, W_ih1, m_ih1, W_hh1, m_hh1, b_ih1, b_hh1);

    copy_out_kernel<<<(BH_) / 256, 256>>>(out);
}